// round 8
// baseline (speedup 1.0000x reference)
#include <cuda_runtime.h>
#include <cuda_bf16.h>

#define D_DIM 41
#define H_DIM 1024
#define W_DIM 1024
#define NMAX  120000
#define HB 19
#define HSIZE (1 << HB)
#define HMASK (HSIZE - 1)
#define NKB 26
#define CAPK 4096
#define FULLM 0xFFFFFFFFu

// ---------------- device state (BSS zero-init; hash idempotent) ----------------
__device__ int g_hkeys[HSIZE];   // 0 = empty, else key+1
__device__ int g_hvals[HSIZE];
__device__ unsigned long long g_pairs_k[NKB][CAPK];
__device__ int g_pcount[NKB];
__device__ volatile unsigned g_bgen;
__device__ unsigned g_bcnt;
__device__ unsigned g_Xh[(size_t)NMAX * 32];   // features bf16-hi packed [row][u]
__device__ unsigned g_Xl[(size_t)NMAX * 32];   // features bf16-lo packed
__device__ float g_P1[4096], g_A0A1[4096];
__device__ float g_S[NKB][4096];   // A0 @ W1[tap]
__device__ float g_Hm[NKB][4096];  // W1[tap] @ A2
__device__ float g_Jm[NKB][4096];  // A1 @ W2[tap]
__device__ float g_G[NKB][4096];   // Hm + Jm
__device__ float g_T[NKB][4096];   // W0k@P1 + S_k@A2 + A0A1@W2k
__device__ unsigned g_P0h[2048], g_P0l[2048];  // A0A1A2 bf16 hi/lo, [n][u]

__device__ __forceinline__ unsigned hash_slot(int key) {
    return ((unsigned)key * 2654435761u) >> (32 - HB);
}
__device__ __forceinline__ unsigned pack_bf16(float a, float b) {
    __nv_bfloat162 p = __floats2bfloat162_rn(a, b);
    return *(unsigned*)&p;
}
__device__ __forceinline__ float bf16rt(float x) {
    return __bfloat162float(__float2bfloat16_rn(x));
}
__device__ __forceinline__ int tap_of(int b) { return b < 13 ? b : b + 1; }

__device__ __forceinline__ int h_lookup(int key) {
    int kp1 = key + 1;
    unsigned h = hash_slot(key);
    for (;;) {
        int k = g_hkeys[h];
        if (k == kp1) return g_hvals[h];
        if (k == 0) return -1;
        h = (h + 1) & HMASK;
    }
}

// neighbor of (b,z,y,x) at bucket's tap; -1 if absent/out of bounds
__device__ int probe_nb(int b, int z, int y, int x, int bucket) {
    int tap = tap_of(bucket);
    int dz = tap / 9 - 1, dy = (tap % 9) / 3 - 1, dx = tap % 3 - 1;
    int nz = z + dz, ny = y + dy, nx = x + dx;
    if (nz < 0 || nz >= D_DIM || ny < 0 || ny >= H_DIM || nx < 0 || nx >= W_DIM)
        return -1;
    return h_lookup(((b * D_DIM + nz) * H_DIM + ny) * W_DIM + nx);
}

// grid barrier: all nb blocks co-resident by construction
__device__ __forceinline__ void grid_sync(int nb) {
    __threadfence();
    __syncthreads();
    if (threadIdx.x == 0) {
        unsigned gen = g_bgen;
        if (atomicAdd(&g_bcnt, 1u) == (unsigned)(nb - 1)) {
            g_bcnt = 0;
            __threadfence();
            g_bgen = gen + 1;
        } else {
            while (g_bgen == gen) __nanosleep(64);
        }
    }
    __syncthreads();
}

// ---------------- 64x64 matrix product helper ----------------
// C = A @ B (row-major). Cs: smem out; else Cg global (accum = atomicAdd).
__device__ __noinline__ void matprod(const float* __restrict__ Ag,
                                     const float* __restrict__ Bg, float* Cg,
                                     float* Cs, bool accum, float* fsm, int tid) {
    float* As = fsm;
    float* Bs = fsm + 4096;
    for (int t = tid; t < 4096; t += 256) { As[t] = Ag[t]; Bs[t] = Bg[t]; }
    __syncthreads();
#pragma unroll
    for (int g = 0; g < 4; g++) {
        int idx4 = tid + g * 256;
        int r = idx4 >> 4, c4 = idx4 & 15;
        float4 acc = make_float4(0.f, 0.f, 0.f, 0.f);
#pragma unroll 16
        for (int k = 0; k < 64; k++) {
            float a = As[r * 64 + k];
            float4 bv = ((float4*)Bs)[k * 16 + c4];
            acc.x += a * bv.x; acc.y += a * bv.y;
            acc.z += a * bv.z; acc.w += a * bv.w;
        }
        int o = r * 64 + c4 * 4;
        if (Cs) {
            *(float4*)&Cs[o] = acc;
        } else if (accum) {
            atomicAdd(&Cg[o + 0], acc.x); atomicAdd(&Cg[o + 1], acc.y);
            atomicAdd(&Cg[o + 2], acc.z); atomicAdd(&Cg[o + 3], acc.w);
        } else {
            *(float4*)&Cg[o] = acc;
        }
    }
    __syncthreads();
}

// ---------------- warp row-vector GEMM: lane holds cols 2l,2l+1 ----------------
__device__ __forceinline__ void rowgemm_s(float x0, float x1,
                                          const float* __restrict__ Wsh,
                                          float& o0, float& o1, int lane) {
    o0 = 0.f; o1 = 0.f;
#pragma unroll 16
    for (int cr = 0; cr < 64; cr++) {
        float xv = __shfl_sync(FULLM, (cr & 1) ? x1 : x0, cr >> 1);
        float2 w = ((const float2*)Wsh)[cr * 32 + lane];
        o0 += xv * w.x; o1 += xv * w.y;
    }
}
__device__ __forceinline__ void rowgemm_g(float x0, float x1,
                                          const float* __restrict__ Wg,
                                          float& o0, float& o1, int lane) {
    o0 = 0.f; o1 = 0.f;
#pragma unroll 16
    for (int cr = 0; cr < 64; cr++) {
        float xv = __shfl_sync(FULLM, (cr & 1) ? x1 : x0, cr >> 1);
        float2 w = __ldg((const float2*)(Wg + cr * 64 + 2 * lane));
        o0 += xv * w.x; o1 += xv * w.y;
    }
}

__device__ __forceinline__ void mma_bf16(float* c, const unsigned* a,
                                         unsigned b0, unsigned b1) {
    asm volatile(
        "mma.sync.aligned.m16n8k16.row.col.f32.bf16.bf16.f32 "
        "{%0,%1,%2,%3}, {%4,%5,%6,%7}, {%8,%9}, {%0,%1,%2,%3};"
        : "+f"(c[0]), "+f"(c[1]), "+f"(c[2]), "+f"(c[3])
        : "r"(a[0]), "r"(a[1]), "r"(a[2]), "r"(a[3]), "r"(b0), "r"(b1));
}

#define MEGA_SMEM 49152

__global__ void __launch_bounds__(256, 3)
k_mega(const float* __restrict__ X, const int* __restrict__ coors,
       const float* __restrict__ Ws, float* __restrict__ out, int N, int nb) {
    extern __shared__ float fsm[];
    int bid = blockIdx.x, tid = threadIdx.x;
    int warp = tid >> 5, lane = tid & 31;
    int gtid = bid * 256 + tid, gn = nb * 256;
    const float* A0 = Ws + (size_t)13 * 4096;
    const float* A1 = Ws + (size_t)(27 + 13) * 4096;
    const float* A2 = Ws + (size_t)(54 + 13) * 4096;

    // ========== W1: resets + insert + pack X + stage-1 mat products ==========
    if (bid == nb - 1 && tid < NKB) g_pcount[tid] = 0;
    for (int t = gtid; t < NKB * 4096; t += gn) ((float*)g_T)[t] = 0.f;
    for (int i = gtid; i < N; i += gn) {
        int b = coors[4 * i + 0], z = coors[4 * i + 1];
        int y = coors[4 * i + 2], x = coors[4 * i + 3];
        int key = ((b * D_DIM + z) * H_DIM + y) * W_DIM + x;
        int kp1 = key + 1;
        unsigned h = hash_slot(key);
        for (;;) {
            int old = atomicCAS(&g_hkeys[h], 0, kp1);
            if (old == 0 || old == kp1) { g_hvals[h] = i; break; }
            h = (h + 1) & HMASK;
        }
    }
    for (int idx = gtid; idx < N * 32; idx += gn) {
        int row = idx >> 5, u = idx & 31;
        float2 v = *(const float2*)&X[(size_t)row * 64 + 2 * u];
        float h0 = bf16rt(v.x), h1 = bf16rt(v.y);
        g_Xh[idx] = pack_bf16(h0, h1);
        g_Xl[idx] = pack_bf16(v.x - h0, v.y - h1);
    }
    if (bid == 0) matprod(A1, A2, g_P1, nullptr, false, fsm, tid);
    else if (bid == 1) matprod(A0, A1, g_A0A1, nullptr, false, fsm, tid);
    else if (bid >= 2 && bid < 28) {
        int a = bid - 2;
        matprod(A0, Ws + (size_t)(27 + tap_of(a)) * 4096, g_S[a], nullptr, false, fsm, tid);
    } else if (bid >= 28 && bid < 54) {
        int b = bid - 28;
        matprod(Ws + (size_t)(27 + tap_of(b)) * 4096, A2, g_Hm[b], nullptr, false, fsm, tid);
    } else if (bid >= 54 && bid < 80) {
        int b = bid - 54;
        matprod(A1, Ws + (size_t)(54 + tap_of(b)) * 4096, g_Jm[b], nullptr, false, fsm, tid);
    }
    grid_sync(nb);

    // ========== W2: build pairs + stage-2 mat products ==========
    for (int i = gtid; i < N; i += gn) {
        int b = coors[4 * i + 0], z = coors[4 * i + 1];
        int y = coors[4 * i + 2], x = coors[4 * i + 3];
        int keys[13]; bool valid[13]; unsigned hh[13];
        int kk = 0;
#pragma unroll
        for (int dz = -1; dz <= 1; dz++)
#pragma unroll
            for (int dy = -1; dy <= 1; dy++)
#pragma unroll
                for (int dx = -1; dx <= 1; dx++) {
                    if (kk >= 13) continue;
                    int nz = z + dz, ny = y + dy, nx = x + dx;
                    bool inb = (nz >= 0) & (nz < D_DIM) & (ny >= 0) &
                               (ny < H_DIM) & (nx >= 0) & (nx < W_DIM);
                    int key = ((b * D_DIM + nz) * H_DIM + ny) * W_DIM + nx;
                    keys[kk] = key + 1; valid[kk] = inb; hh[kk] = hash_slot(key);
                    kk++;
                }
        int first[13];
#pragma unroll
        for (int t = 0; t < 13; t++) first[t] = valid[t] ? g_hkeys[hh[t]] : 0;
#pragma unroll
        for (int t = 0; t < 13; t++) {
            if (!valid[t]) continue;
            int j = -1, k0 = first[t];
            if (k0 == keys[t]) j = g_hvals[hh[t]];
            else if (k0 != 0) {
                unsigned h = (hh[t] + 1) & HMASK;
                for (;;) {
                    int k = g_hkeys[h];
                    if (k == keys[t]) { j = g_hvals[h]; break; }
                    if (k == 0) break;
                    h = (h + 1) & HMASK;
                }
            }
            if (j >= 0) {
                unsigned long long e1 = (unsigned)i | ((unsigned long long)(unsigned)j << 32);
                unsigned long long e2 = (unsigned)j | ((unsigned long long)(unsigned)i << 32);
                int p1 = atomicAdd(&g_pcount[t], 1);
                if (p1 < CAPK) g_pairs_k[t][p1] = e1;
                int p2 = atomicAdd(&g_pcount[25 - t], 1);
                if (p2 < CAPK) g_pairs_k[25 - t][p2] = e2;
            }
        }
    }
    if (bid == 0) {
        matprod(A0, g_P1, nullptr, fsm + 8192, false, fsm, tid);
        float* C = fsm + 8192;
        for (int e = tid; e < 2048; e += 256) {
            int n = e >> 5, u = e & 31;
            float w0 = C[(2 * u) * 64 + n], w1 = C[(2 * u + 1) * 64 + n];
            float h0 = bf16rt(w0), h1 = bf16rt(w1);
            g_P0h[e] = pack_bf16(h0, h1);
            g_P0l[e] = pack_bf16(w0 - h0, w1 - h1);
        }
    } else if (bid >= 1 && bid <= 26) {
        int k = bid - 1;
        matprod(Ws + (size_t)tap_of(k) * 4096, g_P1, g_T[k], nullptr, true, fsm, tid);
    } else if (bid >= 27 && bid <= 52) {
        int k = bid - 27;
        matprod(g_S[k], A2, g_T[k], nullptr, true, fsm, tid);
    } else if (bid >= 53 && bid <= 78) {
        int k = bid - 53;
        matprod(g_A0A1, Ws + (size_t)(54 + tap_of(k)) * 4096, g_T[k], nullptr, true, fsm, tid);
    } else if (bid >= 79 && bid <= 104) {
        int b2 = bid - 79;
        for (int t = tid; t < 4096; t += 256) g_G[b2][t] = g_Hm[b2][t] + g_Jm[b2][t];
    }
    grid_sync(nb);

    // ========== W3: dense out = X @ P0 (warp-autonomous bf16 3-split) ==========
    {
        unsigned* Whs = (unsigned*)fsm;
        unsigned* Wls = Whs + 64 * 36;
        for (int idx4 = tid; idx4 < 512; idx4 += 256) {
            int n = idx4 >> 3, u0 = (idx4 & 7) << 2;
            *(uint4*)&Whs[n * 36 + u0] = ((const uint4*)g_P0h)[idx4];
            *(uint4*)&Wls[n * 36 + u0] = ((const uint4*)g_P0l)[idx4];
        }
        __syncthreads();
        int l4 = lane >> 2, lq = lane & 3;
        int nchunks = (N + 15) >> 4;
        for (int ch = bid * 8 + warp; ch < nchunks; ch += nb * 8) {
            int r0 = ch << 4;
            int rA = (r0 + l4) * 32, rB = (r0 + l4 + 8) * 32;
            float c[8][4];
#pragma unroll
            for (int t = 0; t < 8; t++)
#pragma unroll
                for (int r = 0; r < 4; r++) c[t][r] = 0.f;
#pragma unroll
            for (int ks = 0; ks < 4; ks++) {
                int u0 = ks * 8 + lq;
                unsigned ah[4], al[4];
                ah[0] = g_Xh[rA + u0]; ah[1] = g_Xh[rB + u0];
                ah[2] = g_Xh[rA + u0 + 4]; ah[3] = g_Xh[rB + u0 + 4];
                al[0] = g_Xl[rA + u0]; al[1] = g_Xl[rB + u0];
                al[2] = g_Xl[rA + u0 + 4]; al[3] = g_Xl[rB + u0 + 4];
#pragma unroll
                for (int nt = 0; nt < 8; nt++) {
                    int nbase = (nt * 8 + l4) * 36;
                    mma_bf16(c[nt], ah, Whs[nbase + u0], Whs[nbase + u0 + 4]);
                }
#pragma unroll
                for (int nt = 0; nt < 8; nt++) {
                    int nbase = (nt * 8 + l4) * 36;
                    mma_bf16(c[nt], ah, Wls[nbase + u0], Wls[nbase + u0 + 4]);
                }
#pragma unroll
                for (int nt = 0; nt < 8; nt++) {
                    int nbase = (nt * 8 + l4) * 36;
                    mma_bf16(c[nt], al, Whs[nbase + u0], Whs[nbase + u0 + 4]);
                }
            }
            int row0 = r0 + l4, row1 = r0 + l4 + 8;
#pragma unroll
            for (int nt = 0; nt < 8; nt++) {
                int ncol = nt * 8 + lq * 2;
                if (row0 < N)
                    *(float2*)&out[(size_t)row0 * 64 + ncol] = make_float2(c[nt][0], c[nt][1]);
                if (row1 < N)
                    *(float2*)&out[(size_t)row1 * 64 + ncol] = make_float2(c[nt][2], c[nt][3]);
            }
        }
    }
    grid_sync(nb);

    // ========== W4: correction paths (no more barriers) ==========
    int slices = (nb / 2) / NKB;
    if (slices < 1) slices = 1;
    if (slices > 16) slices = 16;
    int pairb = NKB * slices;

    if (bid < pairb) {
        // 1-hop: out[i] += x0[j] @ T[bucket]
        int bkt = bid / slices, slice = bid % slices;
        float* Tsh = fsm;
        for (int t = tid; t < 4096; t += 256) Tsh[t] = g_T[bkt][t];
        __syncthreads();
        int pc = g_pcount[bkt];
        if (pc > CAPK) pc = CAPK;
        for (int p = slice * 8 + warp; p < pc; p += slices * 8) {
            unsigned long long e = g_pairs_k[bkt][p];
            int i = (int)(e & 0xFFFFFFFFu);
            int j = (int)(e >> 32);
            float2 xv = *(const float2*)&X[(size_t)j * 64 + 2 * lane];
            float o0, o1;
            rowgemm_s(xv.x, xv.y, Tsh, o0, o1, lane);
            atomicAdd(&out[(size_t)i * 64 + 2 * lane], o0);
            atomicAdd(&out[(size_t)i * 64 + 2 * lane + 1], o1);
        }
    } else {
        // 2-hop + 3-hop path enumeration
        int wid2 = (bid - pairb) * 8 + warp;
        int wn = (nb - pairb) * 8;
        for (int bkt = 0; bkt < NKB; bkt++) {
            int pc = g_pcount[bkt];
            if (pc > CAPK) pc = CAPK;
            const float* W2b = Ws + (size_t)(54 + tap_of(bkt)) * 4096;
            for (int p = wid2; p < pc; p += wn) {
                unsigned long long e = g_pairs_k[bkt][p];
                int i = (int)(e & 0xFFFFFFFFu);
                int j = (int)(e >> 32);
                int jb = coors[4 * j], jz = coors[4 * j + 1];
                int jy = coors[4 * j + 2], jx = coors[4 * j + 3];
                int j2f = -1;
                if (lane < NKB) j2f = probe_nb(jb, jz, jy, jx, lane);
                unsigned m2 = __ballot_sync(FULLM, j2f >= 0);
                while (m2) {
                    int f = __ffs(m2) - 1;
                    m2 &= m2 - 1;
                    int j2 = __shfl_sync(FULLM, j2f, f);
                    int a = f, ta = tap_of(a);
                    float2 xv = *(const float2*)&X[(size_t)j2 * 64 + 2 * lane];
                    float t0, t1, u0, u1, s0, s1, v0, v1;
                    rowgemm_g(xv.x, xv.y, Ws + (size_t)ta * 4096, t0, t1, lane);
                    rowgemm_g(t0, t1, g_G[bkt], u0, u1, lane);
                    rowgemm_g(xv.x, xv.y, g_S[a], s0, s1, lane);
                    rowgemm_g(s0, s1, W2b, v0, v1, lane);
                    atomicAdd(&out[(size_t)i * 64 + 2 * lane], u0 + v0);
                    atomicAdd(&out[(size_t)i * 64 + 2 * lane + 1], u1 + v1);
                    // 3-hop through j2
                    int qb = coors[4 * j2], qz = coors[4 * j2 + 1];
                    int qy = coors[4 * j2 + 2], qx = coors[4 * j2 + 3];
                    int j3f = -1;
                    if (lane < NKB) j3f = probe_nb(qb, qz, qy, qx, lane);
                    unsigned m3 = __ballot_sync(FULLM, j3f >= 0);
                    while (m3) {
                        int g3 = __ffs(m3) - 1;
                        m3 &= m3 - 1;
                        int j3 = __shfl_sync(FULLM, j3f, g3);
                        int tc = tap_of(g3);
                        float2 x3 = *(const float2*)&X[(size_t)j3 * 64 + 2 * lane];
                        float p0, p1, q0, q1, r0f, r1f;
                        rowgemm_g(x3.x, x3.y, Ws + (size_t)tc * 4096, p0, p1, lane);
                        rowgemm_g(p0, p1, Ws + (size_t)(27 + ta) * 4096, q0, q1, lane);
                        rowgemm_g(q0, q1, W2b, r0f, r1f, lane);
                        atomicAdd(&out[(size_t)i * 64 + 2 * lane], r0f);
                        atomicAdd(&out[(size_t)i * 64 + 2 * lane + 1], r1f);
                    }
                }
            }
        }
    }
}

// ---------------- launch ----------------
extern "C" void kernel_launch(void* const* d_in, const int* in_sizes, int n_in,
                              void* d_out, int out_size) {
    const float* features = (const float*)d_in[0];
    const float* Ws = (const float*)d_in[1];
    const int* coors = (const int*)d_in[2];
    int N = in_sizes[0] / 64;
    float* out = (float*)d_out;

    cudaFuncSetAttribute(k_mega, cudaFuncAttributeMaxDynamicSharedMemorySize,
                         MEGA_SMEM);
    int dev = 0, nsm = 0, occ = 0;
    cudaGetDevice(&dev);
    cudaDeviceGetAttribute(&nsm, cudaDevAttrMultiProcessorCount, dev);
    cudaOccupancyMaxActiveBlocksPerMultiprocessor(&occ, k_mega, 256, MEGA_SMEM);
    if (occ < 1) occ = 1;
    int nb = occ * nsm;   // exactly co-resident -> grid barriers safe

    k_mega<<<nb, 256, MEGA_SMEM>>>(features, coors, Ws, out, N, nb);
}

// round 9
// speedup vs baseline: 4.5899x; 4.5899x over previous
#include <cuda_runtime.h>
#include <cuda_bf16.h>

#define D_DIM 41
#define H_DIM 1024
#define W_DIM 1024
#define NMAX  120000
#define HB 19
#define HSIZE (1 << HB)
#define HMASK (HSIZE - 1)
#define NKB 26
#define CAPK 4096
#define FULLM 0xFFFFFFFFu

// ---------------- device state (BSS zero-init; hash idempotent) ----------------
__device__ int g_hkeys[HSIZE];   // 0 = empty, else key+1
__device__ int g_hvals[HSIZE];
__device__ unsigned long long g_pairs_k[NKB][CAPK];
__device__ int g_pcount[NKB];
__device__ int g_active[NMAX];
__device__ int g_nactive;
__device__ int g_runtag[NMAX];
__device__ unsigned g_runid;
// barriers: full grid + two group barriers
__device__ volatile unsigned g_bgen;  __device__ unsigned g_bcnt;
__device__ volatile unsigned g_rgen;  __device__ unsigned g_rcnt;
__device__ volatile unsigned g_dgen;  __device__ unsigned g_dcnt;
// packed features + precomputed matrices + chain buffers
__device__ unsigned g_Xh[(size_t)NMAX * 32];
__device__ unsigned g_Xl[(size_t)NMAX * 32];
__device__ float g_P1[4096];
__device__ unsigned g_P0h[2048], g_P0l[2048];
__device__ float g_c0[(size_t)NMAX * 64];
__device__ float g_c1[(size_t)NMAX * 64];
__device__ float g_x1[(size_t)NMAX * 64];
__device__ float g_x2[(size_t)NMAX * 64];

__device__ __forceinline__ unsigned hash_slot(int key) {
    return ((unsigned)key * 2654435761u) >> (32 - HB);
}
__device__ __forceinline__ unsigned pack_bf16(float a, float b) {
    __nv_bfloat162 p = __floats2bfloat162_rn(a, b);
    return *(unsigned*)&p;
}
__device__ __forceinline__ float bf16rt(float x) {
    return __bfloat162float(__float2bfloat16_rn(x));
}
__device__ __forceinline__ int tap_of(int b) { return b < 13 ? b : b + 1; }

// generic group barrier over `count` blocks sharing (gen, cnt)
__device__ __forceinline__ void group_sync(volatile unsigned* gen, unsigned* cnt,
                                           int count) {
    __threadfence();
    __syncthreads();
    if (threadIdx.x == 0) {
        unsigned g = *gen;
        if (atomicAdd(cnt, 1u) == (unsigned)(count - 1)) {
            atomicExch(cnt, 0u);
            __threadfence();
            *gen = g + 1;
        } else {
            while (*gen == g) __nanosleep(64);
        }
        __threadfence();
    }
    __syncthreads();
}

// claim row into active set once per run; zero its c-buffers
__device__ __forceinline__ void claim_active(int r, unsigned runid) {
    if (atomicExch(&g_runtag[r], (int)runid) != (int)runid) {
        int pos = atomicAdd(&g_nactive, 1);
        g_active[pos] = r;
        float4 z = make_float4(0.f, 0.f, 0.f, 0.f);
        float4* c0 = (float4*)&g_c0[(size_t)r * 64];
        float4* c1 = (float4*)&g_c1[(size_t)r * 64];
#pragma unroll
        for (int q = 0; q < 16; q++) { c0[q] = z; c1[q] = z; }
    }
}

// warp: y = xrow(64) @ Wsh(64x64); SET (+base) or atomicAdd
__device__ __forceinline__ void warp_row_gemm(const float* __restrict__ xrow,
                                              const float* __restrict__ Wsh,
                                              float* dst, const float* base,
                                              int lane, bool useAtomic) {
    float2 xv2 = *(const float2*)&xrow[lane * 2];
    float a0 = 0.f, a1 = 0.f;
#pragma unroll
    for (int cr = 0; cr < 64; cr++) {
        float xv = __shfl_sync(FULLM, (cr & 1) ? xv2.y : xv2.x, cr >> 1);
        a0 += xv * Wsh[cr * 64 + lane];
        a1 += xv * Wsh[cr * 64 + lane + 32];
    }
    if (useAtomic) {
        atomicAdd(&dst[lane], a0);
        atomicAdd(&dst[lane + 32], a1);
    } else {
        dst[lane] = a0 + base[lane];
        dst[lane + 32] = a1 + base[lane + 32];
    }
}

__device__ __forceinline__ void stage_w(float* Wsh, const float* __restrict__ src,
                                        int tid) {
#pragma unroll
    for (int it = 0; it < 4; it++) {
        int idx = tid + it * 256;
        ((float4*)Wsh)[idx] = ((const float4*)src)[idx];
    }
}

// one bucket's pairs: dst[i] += Xsrc[j] @ W    (bkt/slice chosen by caller)
__device__ void pair_phase(const float* __restrict__ Xsrc, float* dst,
                           const float* __restrict__ Wtap, float* Wsh,
                           int bkt, int slice, int nslices, int tid) {
    stage_w(Wsh, Wtap, tid);
    __syncthreads();
    int warp = tid >> 5, lane = tid & 31;
    int pc = g_pcount[bkt];
    if (pc > CAPK) pc = CAPK;
    for (int p = slice * 8 + warp; p < pc; p += nslices * 8) {
        unsigned long long e = g_pairs_k[bkt][p];
        int i = (int)(e & 0xFFFFFFFFu);
        int j = (int)(e >> 32);
        warp_row_gemm(Xsrc + (size_t)j * 64, Wsh, dst + (size_t)i * 64, nullptr,
                      lane, true);
    }
}

// xout[a] = xin[a] @ A + cadd[a] over active rows (all nb blocks)
__device__ void x_step(const float* __restrict__ xin, const float* __restrict__ cadd,
                       float* xout, const float* __restrict__ A, float* Wsh,
                       int bid, int tid, int nb, int na) {
    stage_w(Wsh, A, tid);
    __syncthreads();
    int warp = tid >> 5, lane = tid & 31;
    for (int idx = bid * 8 + warp; idx < na; idx += nb * 8) {
        int a = g_active[idx];
        warp_row_gemm(xin + (size_t)a * 64, Wsh, xout + (size_t)a * 64,
                      cadd + (size_t)a * 64, lane, false);
    }
}

// out[a] += cin[a] @ P over active rows (blocks [bid0, bid0+nblk))
__device__ void out_add_step(const float* __restrict__ cin, float* out,
                             const float* __restrict__ P, float* Wsh,
                             int rel, int nblk, int tid, int na) {
    stage_w(Wsh, P, tid);
    __syncthreads();
    int warp = tid >> 5, lane = tid & 31;
    for (int idx = rel * 8 + warp; idx < na; idx += nblk * 8) {
        int a = g_active[idx];
        warp_row_gemm(cin + (size_t)a * 64, Wsh, out + (size_t)a * 64, nullptr,
                      lane, true);
    }
}

// C = A @ B (64x64 row-major); Cs smem out, else Cg
__device__ __noinline__ void matprod(const float* __restrict__ Ag,
                                     const float* __restrict__ Bg, float* Cg,
                                     float* Cs, float* fsm, int tid) {
    float* As = fsm;
    float* Bs = fsm + 4096;
    for (int t = tid; t < 4096; t += 256) { As[t] = Ag[t]; Bs[t] = Bg[t]; }
    __syncthreads();
#pragma unroll
    for (int g = 0; g < 4; g++) {
        int idx4 = tid + g * 256;
        int r = idx4 >> 4, c4 = idx4 & 15;
        float4 acc = make_float4(0.f, 0.f, 0.f, 0.f);
#pragma unroll 16
        for (int k = 0; k < 64; k++) {
            float a = As[r * 64 + k];
            float4 bv = ((float4*)Bs)[k * 16 + c4];
            acc.x += a * bv.x; acc.y += a * bv.y;
            acc.z += a * bv.z; acc.w += a * bv.w;
        }
        int o = r * 64 + c4 * 4;
        if (Cs) *(float4*)&Cs[o] = acc;
        else *(float4*)&Cg[o] = acc;
    }
    __syncthreads();
}

__device__ __forceinline__ void mma_bf16(float* c, const unsigned* a,
                                         unsigned b0, unsigned b1) {
    asm volatile(
        "mma.sync.aligned.m16n8k16.row.col.f32.bf16.bf16.f32 "
        "{%0,%1,%2,%3}, {%4,%5,%6,%7}, {%8,%9}, {%0,%1,%2,%3};"
        : "+f"(c[0]), "+f"(c[1]), "+f"(c[2]), "+f"(c[3])
        : "r"(a[0]), "r"(a[1]), "r"(a[2]), "r"(a[3]), "r"(b0), "r"(b1));
}

#define MEGA_SMEM 49152
#define PAIRB 208   // blocks on pair-gather during split phases (8 per bucket)

__global__ void __launch_bounds__(256, 3)
k_mega(const float* __restrict__ X, const int* __restrict__ coors,
       const float* __restrict__ Ws, float* __restrict__ out, int N, int nb,
       int R) {
    extern __shared__ float fsm[];
    int bid = blockIdx.x, tid = threadIdx.x;
    int warp = tid >> 5, lane = tid & 31;
    const float* A0 = Ws + (size_t)13 * 4096;
    const float* A1 = Ws + (size_t)(27 + 13) * 4096;
    const float* A2 = Ws + (size_t)(54 + 13) * 4096;
    int nd = nb - R;  // dense-side block count

    if (bid < R) {
        // ======== RULEBOOK SIDE: resets + insert, group barrier, build ========
        int gt = bid * 256 + tid, gs = R * 256;
        if (bid == 0) {
            if (tid < NKB) g_pcount[tid] = 0;
            if (tid == 32) g_nactive = 0;
            if (tid == 33) g_runid = g_runid + 1;
        }
        for (int i = gt; i < N; i += gs) {
            int b = coors[4 * i + 0], z = coors[4 * i + 1];
            int y = coors[4 * i + 2], x = coors[4 * i + 3];
            int key = ((b * D_DIM + z) * H_DIM + y) * W_DIM + x;
            int kp1 = key + 1;
            unsigned h = hash_slot(key);
            for (;;) {
                int old = atomicCAS(&g_hkeys[h], 0, kp1);
                if (old == 0 || old == kp1) { g_hvals[h] = i; break; }
                h = (h + 1) & HMASK;
            }
        }
        group_sync(&g_rgen, &g_rcnt, R);
        unsigned runid = *(volatile unsigned*)&g_runid;

        for (int i = gt; i < N; i += gs) {
            int b = coors[4 * i + 0], z = coors[4 * i + 1];
            int y = coors[4 * i + 2], x = coors[4 * i + 3];
            int keys[13]; bool valid[13]; unsigned hh[13];
            int kk = 0;
#pragma unroll
            for (int dz = -1; dz <= 1; dz++)
#pragma unroll
                for (int dy = -1; dy <= 1; dy++)
#pragma unroll
                    for (int dx = -1; dx <= 1; dx++) {
                        if (kk >= 13) continue;
                        int nz = z + dz, ny = y + dy, nx = x + dx;
                        bool inb = (nz >= 0) & (nz < D_DIM) & (ny >= 0) &
                                   (ny < H_DIM) & (nx >= 0) & (nx < W_DIM);
                        int key = ((b * D_DIM + nz) * H_DIM + ny) * W_DIM + nx;
                        keys[kk] = key + 1; valid[kk] = inb;
                        hh[kk] = hash_slot(key);
                        kk++;
                    }
            int first[13];
#pragma unroll
            for (int t = 0; t < 13; t++) first[t] = valid[t] ? g_hkeys[hh[t]] : 0;
#pragma unroll
            for (int t = 0; t < 13; t++) {
                if (!valid[t]) continue;
                int j = -1, k0 = first[t];
                if (k0 == keys[t]) j = g_hvals[hh[t]];
                else if (k0 != 0) {
                    unsigned h = (hh[t] + 1) & HMASK;
                    for (;;) {
                        int k = g_hkeys[h];
                        if (k == keys[t]) { j = g_hvals[h]; break; }
                        if (k == 0) break;
                        h = (h + 1) & HMASK;
                    }
                }
                if (j >= 0) {
                    unsigned long long e1 =
                        (unsigned)i | ((unsigned long long)(unsigned)j << 32);
                    unsigned long long e2 =
                        (unsigned)j | ((unsigned long long)(unsigned)i << 32);
                    int p1 = atomicAdd(&g_pcount[t], 1);
                    if (p1 < CAPK) g_pairs_k[t][p1] = e1;
                    int p2 = atomicAdd(&g_pcount[25 - t], 1);
                    if (p2 < CAPK) g_pairs_k[25 - t][p2] = e2;
                    claim_active(i, runid);
                    claim_active(j, runid);
                }
            }
        }
    } else {
        // ======== DENSE SIDE: pack X + P products, barrier, dense GEMM ========
        int db = bid - R;
        int gt = db * 256 + tid, gs = nd * 256;
        for (int idx = gt; idx < N * 32; idx += gs) {
            int row = idx >> 5, u = idx & 31;
            float2 v = *(const float2*)&X[(size_t)row * 64 + 2 * u];
            float h0 = bf16rt(v.x), h1 = bf16rt(v.y);
            g_Xh[idx] = pack_bf16(h0, h1);
            g_Xl[idx] = pack_bf16(v.x - h0, v.y - h1);
        }
        if (db == 0) {
            matprod(A1, A2, g_P1, nullptr, fsm, tid);
            matprod(A0, g_P1, nullptr, fsm + 8192, fsm, tid);
            float* C = fsm + 8192;
            for (int e = tid; e < 2048; e += 256) {
                int n = e >> 5, u = e & 31;
                float w0 = C[(2 * u) * 64 + n], w1 = C[(2 * u + 1) * 64 + n];
                float h0 = bf16rt(w0), h1 = bf16rt(w1);
                g_P0h[e] = pack_bf16(h0, h1);
                g_P0l[e] = pack_bf16(w0 - h0, w1 - h1);
            }
        }
        group_sync(&g_dgen, &g_dcnt, nd);

        // warp-autonomous dense GEMM: out = X @ P0 (bf16 3-split)
        unsigned* Whs = (unsigned*)fsm;
        unsigned* Wls = Whs + 64 * 36;
        for (int idx4 = tid; idx4 < 512; idx4 += 256) {
            int n = idx4 >> 3, u0 = (idx4 & 7) << 2;
            *(uint4*)&Whs[n * 36 + u0] = ((const uint4*)g_P0h)[idx4];
            *(uint4*)&Wls[n * 36 + u0] = ((const uint4*)g_P0l)[idx4];
        }
        __syncthreads();
        int l4 = lane >> 2, lq = lane & 3;
        int nchunks = (N + 15) >> 4;
        for (int ch = db * 8 + warp; ch < nchunks; ch += nd * 8) {
            int r0 = ch << 4;
            int rA = (r0 + l4) * 32, rB = (r0 + l4 + 8) * 32;
            float c[8][4];
#pragma unroll
            for (int t = 0; t < 8; t++)
#pragma unroll
                for (int r = 0; r < 4; r++) c[t][r] = 0.f;
#pragma unroll
            for (int ks = 0; ks < 4; ks++) {
                int u0 = ks * 8 + lq;
                unsigned ah[4], al[4];
                ah[0] = g_Xh[rA + u0]; ah[1] = g_Xh[rB + u0];
                ah[2] = g_Xh[rA + u0 + 4]; ah[3] = g_Xh[rB + u0 + 4];
                al[0] = g_Xl[rA + u0]; al[1] = g_Xl[rB + u0];
                al[2] = g_Xl[rA + u0 + 4]; al[3] = g_Xl[rB + u0 + 4];
#pragma unroll
                for (int nt = 0; nt < 8; nt++) {
                    int nbase = (nt * 8 + l4) * 36;
                    mma_bf16(c[nt], ah, Whs[nbase + u0], Whs[nbase + u0 + 4]);
                }
#pragma unroll
                for (int nt = 0; nt < 8; nt++) {
                    int nbase = (nt * 8 + l4) * 36;
                    mma_bf16(c[nt], ah, Wls[nbase + u0], Wls[nbase + u0 + 4]);
                }
#pragma unroll
                for (int nt = 0; nt < 8; nt++) {
                    int nbase = (nt * 8 + l4) * 36;
                    mma_bf16(c[nt], al, Whs[nbase + u0], Whs[nbase + u0 + 4]);
                }
            }
            int row0 = r0 + l4, row1 = r0 + l4 + 8;
#pragma unroll
            for (int nt = 0; nt < 8; nt++) {
                int ncol = nt * 8 + lq * 2;
                if (row0 < N)
                    *(float2*)&out[(size_t)row0 * 64 + ncol] =
                        make_float2(c[nt][0], c[nt][1]);
                if (row1 < N)
                    *(float2*)&out[(size_t)row1 * 64 + ncol] =
                        make_float2(c[nt][2], c[nt][3]);
            }
        }
    }
    group_sync(&g_bgen, &g_bcnt, nb);
    int na = g_nactive;

    // ======== sparse correction chain (R7-proven) ========
    // 3a: c0[i] += X[j] @ W0[tap]     (as many blocks as divide evenly)
    {
        int slices = nb / NKB;
        if (bid < NKB * slices)
            pair_phase(X, g_c0, Ws + (size_t)tap_of(bid / slices) * 4096, fsm,
                       bid / slices, bid % slices, slices, tid);
    }
    group_sync(&g_bgen, &g_bcnt, nb);
    // 3b: x1[a] = X[a] @ A0 + c0[a]
    x_step(X, g_c0, g_x1, A0, fsm, bid, tid, nb, na);
    group_sync(&g_bgen, &g_bcnt, nb);
    // 3c: c1[i] += x1[j] @ W1[tap]  ||  out[a] += c0[a] @ P1
    if (bid < PAIRB)
        pair_phase(g_x1, g_c1, Ws + (size_t)(27 + tap_of(bid >> 3)) * 4096, fsm,
                   bid >> 3, bid & 7, 8, tid);
    else
        out_add_step(g_c0, out, g_P1, fsm, bid - PAIRB, nb - PAIRB, tid, na);
    group_sync(&g_bgen, &g_bcnt, nb);
    // 3d: x2[a] = x1[a] @ A1 + c1[a]
    x_step(g_x1, g_c1, g_x2, A1, fsm, bid, tid, nb, na);
    group_sync(&g_bgen, &g_bcnt, nb);
    // 3e: out[i] += x2[j] @ W2[tap]  ||  out[a] += c1[a] @ A2
    if (bid < PAIRB)
        pair_phase(g_x2, out, Ws + (size_t)(54 + tap_of(bid >> 3)) * 4096, fsm,
                   bid >> 3, bid & 7, 8, tid);
    else
        out_add_step(g_c1, out, A2, fsm, bid - PAIRB, nb - PAIRB, tid, na);
}

// ---------------- launch ----------------
extern "C" void kernel_launch(void* const* d_in, const int* in_sizes, int n_in,
                              void* d_out, int out_size) {
    const float* features = (const float*)d_in[0];
    const float* Ws = (const float*)d_in[1];
    const int* coors = (const int*)d_in[2];
    int N = in_sizes[0] / 64;
    float* out = (float*)d_out;

    cudaFuncSetAttribute(k_mega, cudaFuncAttributeMaxDynamicSharedMemorySize,
                         MEGA_SMEM);
    int dev = 0, nsm = 0, occ = 0;
    cudaGetDevice(&dev);
    cudaDeviceGetAttribute(&nsm, cudaDevAttrMultiProcessorCount, dev);
    cudaOccupancyMaxActiveBlocksPerMultiprocessor(&occ, k_mega, 256, MEGA_SMEM);
    if (occ < 1) occ = 1;
    int nb = occ * nsm;     // exactly co-resident -> barriers safe
    int R = nb / 3;         // rulebook-side blocks
    if (R < 1) R = 1;

    k_mega<<<nb, 256, MEGA_SMEM>>>(features, coors, Ws, out, N, nb, R);
}